// round 3
// baseline (speedup 1.0000x reference)
#include <cuda_runtime.h>

#define Bsz  2
#define Nseq 4096
#define Cdim 256
#define Hh   4
#define Dh   64
#define NEGV -1e9f
#define EPSL 1e-5f

#define FLASH_SMEM (4 * 64 * 68 * 4 + 64 * 64)

// Scratch (allocation-free rule: __device__ globals)
__device__ float g_q[Bsz * Hh * Nseq * Dh];
__device__ float g_k[Bsz * Hh * Nseq * Dh];
__device__ float g_v[Bsz * Hh * Nseq * Dh];
__device__ float g_ao[Bsz * Nseq * Cdim];

// ---------------------------------------------------------------------------
// Projection GEMM: Y = X @ W^T + b, output scattered to [B,H,N,D] layout.
// 64x64 tile, K-chunk 16, 256 threads (16x16), 4x4 micro-tile per thread.
// ---------------------------------------------------------------------------
__global__ __launch_bounds__(256) void proj_kernel(const float* __restrict__ X,
                                                   const float* __restrict__ W,
                                                   const float* __restrict__ bias,
                                                   int which)
{
    float* out = (which == 0) ? g_q : (which == 1) ? g_k : g_v;
    __shared__ float sX[16][68];
    __shared__ float sW[16][68];
    int tid = threadIdx.x;
    int tx = tid & 15, ty = tid >> 4;
    int m0 = blockIdx.y * 64, o0 = blockIdx.x * 64;
    float acc[4][4] = {};

    for (int k0 = 0; k0 < Cdim; k0 += 16) {
        int r  = tid >> 2;
        int kq = (tid & 3) * 4;
        float4 xv = *(const float4*)&X[(m0 + r) * Cdim + k0 + kq];
        sX[kq + 0][r] = xv.x; sX[kq + 1][r] = xv.y;
        sX[kq + 2][r] = xv.z; sX[kq + 3][r] = xv.w;
        float4 wv = *(const float4*)&W[(o0 + r) * Cdim + k0 + kq];
        sW[kq + 0][r] = wv.x; sW[kq + 1][r] = wv.y;
        sW[kq + 2][r] = wv.z; sW[kq + 3][r] = wv.w;
        __syncthreads();
        #pragma unroll
        for (int k = 0; k < 16; k++) {
            float4 a  = *(const float4*)&sX[k][ty * 4];
            float4 w4 = *(const float4*)&sW[k][tx * 4];
            float av[4] = {a.x, a.y, a.z, a.w};
            float bv[4] = {w4.x, w4.y, w4.z, w4.w};
            #pragma unroll
            for (int i = 0; i < 4; i++)
                #pragma unroll
                for (int j = 0; j < 4; j++)
                    acc[i][j] = fmaf(av[i], bv[j], acc[i][j]);
        }
        __syncthreads();
    }

    #pragma unroll
    for (int i = 0; i < 4; i++) {
        int m = m0 + ty * 4 + i;
        int b = m >> 12, n = m & (Nseq - 1);
        #pragma unroll
        for (int j = 0; j < 4; j++) {
            int o = o0 + tx * 4 + j;
            int h = o >> 6, dd = o & 63;
            out[(((b * Hh + h) * Nseq) + n) * Dh + dd] = acc[i][j] + bias[o];
        }
    }
}

// ---------------------------------------------------------------------------
// Flash attention with adjacency mask. One CTA = (b, h, 64-query tile).
// BM=BN=64, online softmax, 4x4 per-thread tiles. Output -> [B,N,C] layout.
// ---------------------------------------------------------------------------
__global__ __launch_bounds__(256) void flash_kernel(const int* __restrict__ adj)
{
    extern __shared__ float sm[];
    float* sQ = sm;
    float* sK = sQ + 64 * 68;
    float* sV = sK + 64 * 68;
    float* sP = sV + 64 * 68;
    unsigned char* sAdj = (unsigned char*)(sP + 64 * 68);

    int tid = threadIdx.x;
    int tx = tid & 15, ty = tid >> 4;
    int q0 = blockIdx.x * 64;
    int h = blockIdx.y, b = blockIdx.z;
    const float* Q = g_q + (b * Hh + h) * Nseq * Dh;
    const float* K = g_k + (b * Hh + h) * Nseq * Dh;
    const float* V = g_v + (b * Hh + h) * Nseq * Dh;

    // Load Q tile once: 64 rows x 64 floats
    #pragma unroll
    for (int r4 = 0; r4 < 4; r4++) {
        int fl = tid + 256 * r4;
        int r = fl >> 4, c4 = (fl & 15) * 4;
        *(float4*)&sQ[r * 68 + c4] = *(const float4*)&Q[(q0 + r) * Dh + c4];
    }

    float m_i[4], l_i[4], accO[4][4];
    #pragma unroll
    for (int i = 0; i < 4; i++) {
        m_i[i] = -1e30f; l_i[i] = 0.f;
        #pragma unroll
        for (int j = 0; j < 4; j++) accO[i][j] = 0.f;
    }

    const float scl = 0.125f;  // 1/sqrt(64)

    for (int t = 0; t < Nseq / 64; t++) {
        int kb = t * 64;
        __syncthreads();  // protect sK/sV/sP/sAdj from previous iteration readers
        #pragma unroll
        for (int r4 = 0; r4 < 4; r4++) {
            int fl = tid + 256 * r4;
            int r = fl >> 4, c4 = (fl & 15) * 4;
            *(float4*)&sK[r * 68 + c4] = *(const float4*)&K[(kb + r) * Dh + c4];
            *(float4*)&sV[r * 68 + c4] = *(const float4*)&V[(kb + r) * Dh + c4];
            int4 av = *(const int4*)&adj[(b * Nseq + q0 + r) * Nseq + kb + c4];
            sAdj[r * 64 + c4 + 0] = (unsigned char)(av.x != 0);
            sAdj[r * 64 + c4 + 1] = (unsigned char)(av.y != 0);
            sAdj[r * 64 + c4 + 2] = (unsigned char)(av.z != 0);
            sAdj[r * 64 + c4 + 3] = (unsigned char)(av.w != 0);
        }
        __syncthreads();

        // S = scale * Q K^T with mask
        float s[4][4] = {};
        #pragma unroll 4
        for (int d = 0; d < 64; d += 4) {
            float4 qv[4], kv[4];
            #pragma unroll
            for (int i = 0; i < 4; i++) qv[i] = *(const float4*)&sQ[(ty * 4 + i) * 68 + d];
            #pragma unroll
            for (int j = 0; j < 4; j++) kv[j] = *(const float4*)&sK[(tx * 4 + j) * 68 + d];
            #pragma unroll
            for (int i = 0; i < 4; i++)
                #pragma unroll
                for (int j = 0; j < 4; j++)
                    s[i][j] += qv[i].x * kv[j].x + qv[i].y * kv[j].y +
                               qv[i].z * kv[j].z + qv[i].w * kv[j].w;
        }

        // mask + online softmax (row groups of 16 lanes share a row set)
        #pragma unroll
        for (int i = 0; i < 4; i++) {
            float mx = -1e30f;
            #pragma unroll
            for (int j = 0; j < 4; j++) {
                bool a = sAdj[(ty * 4 + i) * 64 + tx * 4 + j] != 0;
                float sv = a ? s[i][j] * scl : NEGV;
                s[i][j] = sv;
                mx = fmaxf(mx, sv);
            }
            #pragma unroll
            for (int off = 8; off >= 1; off >>= 1)
                mx = fmaxf(mx, __shfl_xor_sync(0xffffffffu, mx, off, 16));
            float mnew = fmaxf(m_i[i], mx);
            float alpha = __expf(m_i[i] - mnew);
            m_i[i] = mnew;
            float rs = 0.f;
            #pragma unroll
            for (int j = 0; j < 4; j++) {
                float pv = __expf(s[i][j] - mnew);  // masked -> exp(<-1e8) == 0
                rs += pv;
                sP[(ty * 4 + i) * 68 + tx * 4 + j] = pv;
            }
            #pragma unroll
            for (int off = 8; off >= 1; off >>= 1)
                rs += __shfl_xor_sync(0xffffffffu, rs, off, 16);
            l_i[i] = l_i[i] * alpha + rs;
            #pragma unroll
            for (int j = 0; j < 4; j++) accO[i][j] *= alpha;
        }
        __syncthreads();

        // O += P @ V
        #pragma unroll 4
        for (int k = 0; k < 64; k++) {
            float4 vv = *(const float4*)&sV[k * 68 + tx * 4];
            #pragma unroll
            for (int i = 0; i < 4; i++) {
                float pv = sP[(ty * 4 + i) * 68 + k];
                accO[i][0] = fmaf(pv, vv.x, accO[i][0]);
                accO[i][1] = fmaf(pv, vv.y, accO[i][1]);
                accO[i][2] = fmaf(pv, vv.z, accO[i][2]);
                accO[i][3] = fmaf(pv, vv.w, accO[i][3]);
            }
        }
    }

    #pragma unroll
    for (int i = 0; i < 4; i++) {
        float inv = 1.f / l_i[i];
        int q = q0 + ty * 4 + i;
        #pragma unroll
        for (int j = 0; j < 4; j++)
            g_ao[(b * Nseq + q) * Cdim + h * Dh + tx * 4 + j] = accO[i][j] * inv;
    }
}

// ---------------------------------------------------------------------------
// Out-proj + bias + LayerNorm, fused. One CTA computes 32 full output rows
// (all 256 cols), so LN stats live in a single warp per 4 rows.
// ---------------------------------------------------------------------------
__global__ __launch_bounds__(256) void outln_kernel(const float* __restrict__ Wo,
                                                    const float* __restrict__ bo,
                                                    const float* __restrict__ gamma,
                                                    const float* __restrict__ beta,
                                                    float* __restrict__ out)
{
    __shared__ float sX[32][36];
    __shared__ float sW[32][260];
    int tid = threadIdx.x;
    int tx = tid & 31, ty = tid >> 5;
    int m0 = blockIdx.x * 32;
    float acc[4][8] = {};

    for (int k0 = 0; k0 < Cdim; k0 += 32) {
        {
            int r = tid >> 3, c4 = (tid & 7) * 4;
            *(float4*)&sX[r][c4] = *(const float4*)&g_ao[(m0 + r) * Cdim + k0 + c4];
        }
        #pragma unroll
        for (int w4 = 0; w4 < 8; w4++) {
            int fl = tid + 256 * w4;
            int o = fl >> 3, c4 = (fl & 7) * 4;
            float4 wv = *(const float4*)&Wo[o * Cdim + k0 + c4];
            sW[c4 + 0][o] = wv.x; sW[c4 + 1][o] = wv.y;
            sW[c4 + 2][o] = wv.z; sW[c4 + 3][o] = wv.w;
        }
        __syncthreads();
        #pragma unroll 8
        for (int k = 0; k < 32; k++) {
            float xv[4];
            #pragma unroll
            for (int i = 0; i < 4; i++) xv[i] = sX[ty * 4 + i][k];
            #pragma unroll
            for (int jj = 0; jj < 8; jj++) {
                float wv = sW[k][tx + 32 * jj];
                #pragma unroll
                for (int i = 0; i < 4; i++)
                    acc[i][jj] = fmaf(xv[i], wv, acc[i][jj]);
            }
        }
        __syncthreads();
    }

    // bias + LayerNorm: warp ty owns rows m0+4ty .. m0+4ty+3 entirely
    #pragma unroll
    for (int i = 0; i < 4; i++) {
        float sum = 0.f, sq = 0.f;
        #pragma unroll
        for (int jj = 0; jj < 8; jj++) {
            float y = acc[i][jj] + bo[tx + 32 * jj];
            acc[i][jj] = y;
            sum += y; sq += y * y;
        }
        #pragma unroll
        for (int off = 16; off >= 1; off >>= 1) {
            sum += __shfl_xor_sync(0xffffffffu, sum, off);
            sq  += __shfl_xor_sync(0xffffffffu, sq, off);
        }
        float mu  = sum * (1.f / 256.f);
        float var = sq * (1.f / 256.f) - mu * mu;
        float rst = rsqrtf(var + EPSL);
        int row = m0 + ty * 4 + i;
        #pragma unroll
        for (int jj = 0; jj < 8; jj++) {
            int c = tx + 32 * jj;
            out[row * Cdim + c] = (acc[i][jj] - mu) * rst * gamma[c] + beta[c];
        }
    }
}

// ---------------------------------------------------------------------------
extern "C" void kernel_launch(void* const* d_in, const int* in_sizes, int n_in,
                              void* d_out, int out_size)
{
    const float* x     = (const float*)d_in[0];
    const int*   adj   = (const int*)  d_in[1];
    const float* Wq    = (const float*)d_in[2];
    const float* bq    = (const float*)d_in[3];
    const float* Wk    = (const float*)d_in[4];
    const float* bk    = (const float*)d_in[5];
    const float* Wv    = (const float*)d_in[6];
    const float* bv    = (const float*)d_in[7];
    const float* Wo    = (const float*)d_in[8];
    const float* bo    = (const float*)d_in[9];
    const float* gamma = (const float*)d_in[10];
    const float* beta  = (const float*)d_in[11];
    float* out = (float*)d_out;

    dim3 pgrid(Cdim / 64, (Bsz * Nseq) / 64);
    proj_kernel<<<pgrid, 256>>>(x, Wq, bq, 0);
    proj_kernel<<<pgrid, 256>>>(x, Wk, bk, 1);
    proj_kernel<<<pgrid, 256>>>(x, Wv, bv, 2);

    cudaFuncSetAttribute(flash_kernel,
                         cudaFuncAttributeMaxDynamicSharedMemorySize, FLASH_SMEM);
    dim3 fgrid(Nseq / 64, Hh, Bsz);
    flash_kernel<<<fgrid, 256, FLASH_SMEM>>>(adj);

    outln_kernel<<<(Bsz * Nseq) / 32, 256>>>(Wo, bo, gamma, beta, out);
}

// round 4
// speedup vs baseline: 2.7571x; 2.7571x over previous
#include <cuda_runtime.h>

#define Bsz  2
#define Nseq 4096
#define Cdim 256
#define Hh   4
#define Dh   64
#define NEGV -1e9f
#define EPSL 1e-5f

// Flash smem: Q(64x68) K(64x68) P(64x68) V(64x72) floats + 128 uint adj bits
#define PADK 68
#define PADV 72
#define OFF_Q 0
#define OFF_K (64 * PADK)
#define OFF_V (2 * 64 * PADK)
#define OFF_P (2 * 64 * PADK + 64 * PADV)
#define FLASH_FLOATS (3 * 64 * PADK + 64 * PADV)
#define FLASH_SMEM (FLASH_FLOATS * 4 + 128 * 4)

// Scratch (allocation-free rule: __device__ globals)
__device__ float g_q[Bsz * Hh * Nseq * Dh];
__device__ float g_k[Bsz * Hh * Nseq * Dh];
__device__ float g_v[Bsz * Hh * Nseq * Dh];
__device__ float g_ao[Bsz * Nseq * Cdim];

// ---------------------------------------------------------------------------
// helpers
// ---------------------------------------------------------------------------
__device__ __forceinline__ float tf32r(float x)
{
    unsigned u;
    asm("cvt.rna.tf32.f32 %0, %1;" : "=r"(u) : "f"(x));
    return __uint_as_float(u);
}

__device__ __forceinline__ void mma_tf32(float* d, const float* a, float b0, float b1)
{
    asm volatile(
        "mma.sync.aligned.m16n8k8.row.col.f32.tf32.tf32.f32 "
        "{%0,%1,%2,%3}, {%4,%5,%6,%7}, {%8,%9}, {%0,%1,%2,%3};"
        : "+f"(d[0]), "+f"(d[1]), "+f"(d[2]), "+f"(d[3])
        : "r"(__float_as_uint(a[0])), "r"(__float_as_uint(a[1])),
          "r"(__float_as_uint(a[2])), "r"(__float_as_uint(a[3])),
          "r"(__float_as_uint(b0)), "r"(__float_as_uint(b1)));
}

// ---------------------------------------------------------------------------
// Projection GEMM: Y = X @ W^T + b, output scattered to [B,H,N,D] layout.
// (unchanged from passing round-1 version)
// ---------------------------------------------------------------------------
__global__ __launch_bounds__(256) void proj_kernel(const float* __restrict__ X,
                                                   const float* __restrict__ W,
                                                   const float* __restrict__ bias,
                                                   int which)
{
    float* out = (which == 0) ? g_q : (which == 1) ? g_k : g_v;
    __shared__ float sX[16][68];
    __shared__ float sW[16][68];
    int tid = threadIdx.x;
    int tx = tid & 15, ty = tid >> 4;
    int m0 = blockIdx.y * 64, o0 = blockIdx.x * 64;
    float acc[4][4] = {};

    for (int k0 = 0; k0 < Cdim; k0 += 16) {
        int r  = tid >> 2;
        int kq = (tid & 3) * 4;
        float4 xv = *(const float4*)&X[(m0 + r) * Cdim + k0 + kq];
        sX[kq + 0][r] = xv.x; sX[kq + 1][r] = xv.y;
        sX[kq + 2][r] = xv.z; sX[kq + 3][r] = xv.w;
        float4 wv = *(const float4*)&W[(o0 + r) * Cdim + k0 + kq];
        sW[kq + 0][r] = wv.x; sW[kq + 1][r] = wv.y;
        sW[kq + 2][r] = wv.z; sW[kq + 3][r] = wv.w;
        __syncthreads();
        #pragma unroll
        for (int k = 0; k < 16; k++) {
            float4 a  = *(const float4*)&sX[k][ty * 4];
            float4 w4 = *(const float4*)&sW[k][tx * 4];
            float av[4] = {a.x, a.y, a.z, a.w};
            float bv[4] = {w4.x, w4.y, w4.z, w4.w};
            #pragma unroll
            for (int i = 0; i < 4; i++)
                #pragma unroll
                for (int j = 0; j < 4; j++)
                    acc[i][j] = fmaf(av[i], bv[j], acc[i][j]);
        }
        __syncthreads();
    }

    #pragma unroll
    for (int i = 0; i < 4; i++) {
        int m = m0 + ty * 4 + i;
        int b = m >> 12, n = m & (Nseq - 1);
        #pragma unroll
        for (int j = 0; j < 4; j++) {
            int o = o0 + tx * 4 + j;
            int h = o >> 6, dd = o & 63;
            out[(((b * Hh + h) * Nseq) + n) * Dh + dd] = acc[i][j] + bias[o];
        }
    }
}

// ---------------------------------------------------------------------------
// Flash attention with adjacency mask — tf32 tensor-core version.
// CTA = 128 threads (4 warps), BM = 64 query rows (16 per warp), BN = 64.
// Q pre-scaled by 0.125*log2(e); softmax in exp2 domain.
// ---------------------------------------------------------------------------
__global__ __launch_bounds__(128) void flash_kernel(const int* __restrict__ adj)
{
    extern __shared__ float sm[];
    float* sQ = sm + OFF_Q;
    float* sK = sm + OFF_K;
    float* sV = sm + OFF_V;
    float* sP = sm + OFF_P;
    unsigned* sAdjB = (unsigned*)(sm + FLASH_FLOATS);

    int tid  = threadIdx.x;
    int lane = tid & 31;
    int warp = tid >> 5;
    int wrow0 = warp * 16;             // this warp's query-row block within tile
    int q0 = blockIdx.x * 64;
    int h = blockIdx.y, b = blockIdx.z;

    const float* Q = g_q + (b * Hh + h) * Nseq * Dh;
    const float* K = g_k + (b * Hh + h) * Nseq * Dh;
    const float* V = g_v + (b * Hh + h) * Nseq * Dh;

    const float qscale = 0.125f * 1.44269504089f;   // 1/sqrt(64) * log2(e)

    // ---- stage Q (scaled, tf32) ----
    #pragma unroll
    for (int i = 0; i < 8; i++) {
        int fl = tid + 128 * i;
        int r = fl >> 4, c4 = (fl & 15) * 4;
        float4 v = *(const float4*)&Q[(q0 + r) * Dh + c4];
        float4 o;
        o.x = tf32r(v.x * qscale); o.y = tf32r(v.y * qscale);
        o.z = tf32r(v.z * qscale); o.w = tf32r(v.w * qscale);
        *(float4*)&sQ[r * PADK + c4] = o;
    }
    __syncthreads();

    // ---- Q A-fragments to registers (held for whole kernel) ----
    float qa[8][4];
    {
        int r = wrow0 + (lane >> 2);
        #pragma unroll
        for (int k = 0; k < 8; k++) {
            int c = k * 8 + (lane & 3);
            qa[k][0] = sQ[r * PADK + c];
            qa[k][1] = sQ[(r + 8) * PADK + c];
            qa[k][2] = sQ[r * PADK + c + 4];
            qa[k][3] = sQ[(r + 8) * PADK + c + 4];
        }
    }

    float o[8][4];
    #pragma unroll
    for (int n = 0; n < 8; n++)
        #pragma unroll
        for (int j = 0; j < 4; j++) o[n][j] = 0.f;
    float mA = -1e30f, mB = -1e30f, lA = 0.f, lB = 0.f;

    int rA = wrow0 + (lane >> 2);       // local query row (and rA+8)

    for (int t = 0; t < Nseq / 64; t++) {
        int kb = t * 64;
        __syncthreads();   // previous tile consumers done with sK/sV/sAdjB

        // ---- stage K, V (tf32) ----
        #pragma unroll
        for (int i = 0; i < 8; i++) {
            int fl = tid + 128 * i;
            int r = fl >> 4, c4 = (fl & 15) * 4;
            float4 kv = *(const float4*)&K[(kb + r) * Dh + c4];
            float4 ko;
            ko.x = tf32r(kv.x); ko.y = tf32r(kv.y);
            ko.z = tf32r(kv.z); ko.w = tf32r(kv.w);
            *(float4*)&sK[r * PADK + c4] = ko;
            float4 vv = *(const float4*)&V[(kb + r) * Dh + c4];
            float4 vo;
            vo.x = tf32r(vv.x); vo.y = tf32r(vv.y);
            vo.z = tf32r(vv.z); vo.w = tf32r(vv.w);
            *(float4*)&sV[r * PADV + c4] = vo;
        }
        // ---- stage adjacency as bitmask: thread t -> (row t>>1, half t&1) ----
        {
            int qrow = tid >> 1, half = tid & 1;
            const int4* ap = (const int4*)&adj[((size_t)(b * Nseq + q0 + qrow)) * Nseq
                                               + kb + half * 32];
            unsigned m = 0;
            #pragma unroll
            for (int i = 0; i < 8; i++) {
                int4 a = ap[i];
                m |= (unsigned)(a.x != 0) << (4 * i);
                m |= (unsigned)(a.y != 0) << (4 * i + 1);
                m |= (unsigned)(a.z != 0) << (4 * i + 2);
                m |= (unsigned)(a.w != 0) << (4 * i + 3);
            }
            sAdjB[qrow * 2 + half] = m;
        }
        __syncthreads();

        // ---- S = Qs @ K^T (already in log2 units) ----
        float s[8][4];
        #pragma unroll
        for (int n = 0; n < 8; n++)
            #pragma unroll
            for (int j = 0; j < 4; j++) s[n][j] = 0.f;
        #pragma unroll
        for (int k = 0; k < 8; k++) {
            #pragma unroll
            for (int n = 0; n < 8; n++) {
                int ridx = (n * 8 + (lane >> 2)) * PADK + k * 8 + (lane & 3);
                mma_tf32(s[n], qa[k], sK[ridx], sK[ridx + 4]);
            }
        }

        // ---- mask + online softmax ----
        unsigned a0m = sAdjB[rA * 2], a1m = sAdjB[rA * 2 + 1];
        unsigned b0m = sAdjB[(rA + 8) * 2], b1m = sAdjB[(rA + 8) * 2 + 1];
        float mxA = -1e30f, mxB = -1e30f;
        #pragma unroll
        for (int n = 0; n < 8; n++) {
            int c = n * 8 + 2 * (lane & 3);
            int sh = c & 31;
            unsigned wA = (n < 4) ? a0m : a1m;
            unsigned wB = (n < 4) ? b0m : b1m;
            s[n][0] = ((wA >> sh) & 1u) ? s[n][0] : NEGV;
            s[n][1] = ((wA >> (sh + 1)) & 1u) ? s[n][1] : NEGV;
            s[n][2] = ((wB >> sh) & 1u) ? s[n][2] : NEGV;
            s[n][3] = ((wB >> (sh + 1)) & 1u) ? s[n][3] : NEGV;
            mxA = fmaxf(mxA, fmaxf(s[n][0], s[n][1]));
            mxB = fmaxf(mxB, fmaxf(s[n][2], s[n][3]));
        }
        mxA = fmaxf(mxA, __shfl_xor_sync(0xffffffffu, mxA, 1));
        mxA = fmaxf(mxA, __shfl_xor_sync(0xffffffffu, mxA, 2));
        mxB = fmaxf(mxB, __shfl_xor_sync(0xffffffffu, mxB, 1));
        mxB = fmaxf(mxB, __shfl_xor_sync(0xffffffffu, mxB, 2));

        float mnA = fmaxf(mA, mxA), mnB = fmaxf(mB, mxB);
        float alA = exp2f(mA - mnA), alB = exp2f(mB - mnB);
        mA = mnA; mB = mnB;

        float suA = 0.f, suB = 0.f;
        #pragma unroll
        for (int n = 0; n < 8; n++) {
            int c = n * 8 + 2 * (lane & 3);
            float p0 = exp2f(s[n][0] - mnA);
            float p1 = exp2f(s[n][1] - mnA);
            float p2 = exp2f(s[n][2] - mnB);
            float p3 = exp2f(s[n][3] - mnB);
            suA += p0 + p1; suB += p2 + p3;
            float2 wa; wa.x = tf32r(p0); wa.y = tf32r(p1);
            *(float2*)&sP[rA * PADK + c] = wa;
            float2 wb; wb.x = tf32r(p2); wb.y = tf32r(p3);
            *(float2*)&sP[(rA + 8) * PADK + c] = wb;
        }
        suA += __shfl_xor_sync(0xffffffffu, suA, 1);
        suA += __shfl_xor_sync(0xffffffffu, suA, 2);
        suB += __shfl_xor_sync(0xffffffffu, suB, 1);
        suB += __shfl_xor_sync(0xffffffffu, suB, 2);
        lA = lA * alA + suA;
        lB = lB * alB + suB;
        #pragma unroll
        for (int n = 0; n < 8; n++) {
            o[n][0] *= alA; o[n][1] *= alA;
            o[n][2] *= alB; o[n][3] *= alB;
        }
        __syncwarp();   // sP (per-warp region) visible to whole warp

        // ---- O += P @ V ----
        #pragma unroll
        for (int k = 0; k < 8; k++) {
            float pa[4];
            int pc = k * 8 + (lane & 3);
            pa[0] = sP[rA * PADK + pc];
            pa[1] = sP[(rA + 8) * PADK + pc];
            pa[2] = sP[rA * PADK + pc + 4];
            pa[3] = sP[(rA + 8) * PADK + pc + 4];
            #pragma unroll
            for (int n = 0; n < 8; n++) {
                int vidx = (k * 8 + (lane & 3)) * PADV + n * 8 + (lane >> 2);
                mma_tf32(o[n], pa, sV[vidx], sV[vidx + 4 * PADV]);
            }
        }
    }

    // ---- normalize + write to [B,N,C] ----
    float ivA = 1.f / lA, ivB = 1.f / lB;
    int gr = b * Nseq + q0 + rA;
    #pragma unroll
    for (int n = 0; n < 8; n++) {
        int c = h * Dh + n * 8 + 2 * (lane & 3);
        float2 wa; wa.x = o[n][0] * ivA; wa.y = o[n][1] * ivA;
        *(float2*)&g_ao[(size_t)gr * Cdim + c] = wa;
        float2 wb; wb.x = o[n][2] * ivB; wb.y = o[n][3] * ivB;
        *(float2*)&g_ao[(size_t)(gr + 8) * Cdim + c] = wb;
    }
}

// ---------------------------------------------------------------------------
// Out-proj + bias + LayerNorm, fused. (unchanged from passing round-1 version)
// ---------------------------------------------------------------------------
__global__ __launch_bounds__(256) void outln_kernel(const float* __restrict__ Wo,
                                                    const float* __restrict__ bo,
                                                    const float* __restrict__ gamma,
                                                    const float* __restrict__ beta,
                                                    float* __restrict__ out)
{
    __shared__ float sX[32][36];
    __shared__ float sW[32][260];
    int tid = threadIdx.x;
    int tx = tid & 31, ty = tid >> 5;
    int m0 = blockIdx.x * 32;
    float acc[4][8] = {};

    for (int k0 = 0; k0 < Cdim; k0 += 32) {
        {
            int r = tid >> 3, c4 = (tid & 7) * 4;
            *(float4*)&sX[r][c4] = *(const float4*)&g_ao[(m0 + r) * Cdim + k0 + c4];
        }
        #pragma unroll
        for (int w4 = 0; w4 < 8; w4++) {
            int fl = tid + 256 * w4;
            int o = fl >> 3, c4 = (fl & 7) * 4;
            float4 wv = *(const float4*)&Wo[o * Cdim + k0 + c4];
            sW[c4 + 0][o] = wv.x; sW[c4 + 1][o] = wv.y;
            sW[c4 + 2][o] = wv.z; sW[c4 + 3][o] = wv.w;
        }
        __syncthreads();
        #pragma unroll 8
        for (int k = 0; k < 32; k++) {
            float xv[4];
            #pragma unroll
            for (int i = 0; i < 4; i++) xv[i] = sX[ty * 4 + i][k];
            #pragma unroll
            for (int jj = 0; jj < 8; jj++) {
                float wv = sW[k][tx + 32 * jj];
                #pragma unroll
                for (int i = 0; i < 4; i++)
                    acc[i][jj] = fmaf(xv[i], wv, acc[i][jj]);
            }
        }
        __syncthreads();
    }

    #pragma unroll
    for (int i = 0; i < 4; i++) {
        float sum = 0.f, sq = 0.f;
        #pragma unroll
        for (int jj = 0; jj < 8; jj++) {
            float y = acc[i][jj] + bo[tx + 32 * jj];
            acc[i][jj] = y;
            sum += y; sq += y * y;
        }
        #pragma unroll
        for (int off = 16; off >= 1; off >>= 1) {
            sum += __shfl_xor_sync(0xffffffffu, sum, off);
            sq  += __shfl_xor_sync(0xffffffffu, sq, off);
        }
        float mu  = sum * (1.f / 256.f);
        float var = sq * (1.f / 256.f) - mu * mu;
        float rst = rsqrtf(var + EPSL);
        int row = m0 + ty * 4 + i;
        #pragma unroll
        for (int jj = 0; jj < 8; jj++) {
            int c = tx + 32 * jj;
            out[row * Cdim + c] = (acc[i][jj] - mu) * rst * gamma[c] + beta[c];
        }
    }
}

// ---------------------------------------------------------------------------
extern "C" void kernel_launch(void* const* d_in, const int* in_sizes, int n_in,
                              void* d_out, int out_size)
{
    const float* x     = (const float*)d_in[0];
    const int*   adj   = (const int*)  d_in[1];
    const float* Wq    = (const float*)d_in[2];
    const float* bq    = (const float*)d_in[3];
    const float* Wk    = (const float*)d_in[4];
    const float* bk    = (const float*)d_in[5];
    const float* Wv    = (const float*)d_in[6];
    const float* bv    = (const float*)d_in[7];
    const float* Wo    = (const float*)d_in[8];
    const float* bo    = (const float*)d_in[9];
    const float* gamma = (const float*)d_in[10];
    const float* beta  = (const float*)d_in[11];
    float* out = (float*)d_out;

    dim3 pgrid(Cdim / 64, (Bsz * Nseq) / 64);
    proj_kernel<<<pgrid, 256>>>(x, Wq, bq, 0);
    proj_kernel<<<pgrid, 256>>>(x, Wk, bk, 1);
    proj_kernel<<<pgrid, 256>>>(x, Wv, bv, 2);

    cudaFuncSetAttribute(flash_kernel,
                         cudaFuncAttributeMaxDynamicSharedMemorySize, FLASH_SMEM);
    dim3 fgrid(Nseq / 64, Hh, Bsz);
    flash_kernel<<<fgrid, 128, FLASH_SMEM>>>(adj);

    outln_kernel<<<(Bsz * Nseq) / 32, 256>>>(Wo, bo, gamma, beta, out);
}

// round 7
// speedup vs baseline: 5.0669x; 1.8377x over previous
#include <cuda_runtime.h>
#include <cuda_fp16.h>

#define Bsz  2
#define Nseq 4096
#define Cdim 256
#define Hh   4
#define Dh   64
#define NEGV -1e9f
#define EPSL 1e-5f
#define HPAD 72   // halves per smem row (144B = 36 words = 4 mod 32 banks)

// Scratch (allocation-free rule: __device__ globals)
__device__ __half  g_q[Bsz * Hh * Nseq * Dh];
__device__ __half  g_k[Bsz * Hh * Nseq * Dh];
__device__ __half  g_v[Bsz * Hh * Nseq * Dh];
__device__ float   g_ao[Bsz * Nseq * Cdim];
__device__ unsigned g_adjb[Bsz * Nseq * (Nseq / 32)];

// ---------------------------------------------------------------------------
// helpers
// ---------------------------------------------------------------------------
__device__ __forceinline__ unsigned sa(const void* p)
{
    return (unsigned)__cvta_generic_to_shared(p);
}

__device__ __forceinline__ void ldsm4(unsigned* r, unsigned a)
{
    asm volatile("ldmatrix.sync.aligned.m8n8.x4.shared.b16 {%0,%1,%2,%3}, [%4];"
                 : "=r"(r[0]), "=r"(r[1]), "=r"(r[2]), "=r"(r[3]) : "r"(a));
}

__device__ __forceinline__ void ldsm4t(unsigned* r, unsigned a)
{
    asm volatile("ldmatrix.sync.aligned.m8n8.x4.trans.shared.b16 {%0,%1,%2,%3}, [%4];"
                 : "=r"(r[0]), "=r"(r[1]), "=r"(r[2]), "=r"(r[3]) : "r"(a));
}

__device__ __forceinline__ void mma16(float* d, const unsigned* a, unsigned b0, unsigned b1)
{
    asm volatile(
        "mma.sync.aligned.m16n8k16.row.col.f32.f16.f16.f32 "
        "{%0,%1,%2,%3}, {%4,%5,%6,%7}, {%8,%9}, {%0,%1,%2,%3};"
        : "+f"(d[0]), "+f"(d[1]), "+f"(d[2]), "+f"(d[3])
        : "r"(a[0]), "r"(a[1]), "r"(a[2]), "r"(a[3]), "r"(b0), "r"(b1));
}

// ---------------------------------------------------------------------------
// adj -> bitmask pre-pass. One warp handles 32 consecutive adj ints -> 1 word.
// ---------------------------------------------------------------------------
__global__ __launch_bounds__(256) void pack_adj_kernel(const int* __restrict__ adj)
{
    int gid = blockIdx.x * 256 + threadIdx.x;
    unsigned m = __ballot_sync(0xffffffffu, adj[gid] != 0);
    if ((threadIdx.x & 31) == 0) g_adjb[gid >> 5] = m;
}

// ---------------------------------------------------------------------------
// Fused QKV projection: Y = X @ W^T + b -> [B,H,N,D] fp16 (Q pre-scaled).
// blockIdx.z selects q/k/v. 64x64 tile, 256 threads, 4x4 micro-tiles.
// ---------------------------------------------------------------------------
__global__ __launch_bounds__(256) void proj_kernel(const float* __restrict__ X,
                                                   const float* __restrict__ Wq,
                                                   const float* __restrict__ bq,
                                                   const float* __restrict__ Wk,
                                                   const float* __restrict__ bk,
                                                   const float* __restrict__ Wv,
                                                   const float* __restrict__ bv)
{
    int which = blockIdx.z;
    const float* W    = (which == 0) ? Wq : (which == 1) ? Wk : Wv;
    const float* bias = (which == 0) ? bq : (which == 1) ? bk : bv;
    __half* out       = (which == 0) ? g_q : (which == 1) ? g_k : g_v;
    float oscale      = (which == 0) ? 0.125f * 1.44269504089f : 1.f;

    __shared__ float sX[16][68];
    __shared__ float sW[16][68];
    int tid = threadIdx.x;
    int tx = tid & 15, ty = tid >> 4;
    int m0 = blockIdx.y * 64, o0 = blockIdx.x * 64;
    float acc[4][4] = {};

    for (int k0 = 0; k0 < Cdim; k0 += 16) {
        int r  = tid >> 2;
        int kq = (tid & 3) * 4;
        float4 xv = *(const float4*)&X[(m0 + r) * Cdim + k0 + kq];
        sX[kq + 0][r] = xv.x; sX[kq + 1][r] = xv.y;
        sX[kq + 2][r] = xv.z; sX[kq + 3][r] = xv.w;
        float4 wv = *(const float4*)&W[(o0 + r) * Cdim + k0 + kq];
        sW[kq + 0][r] = wv.x; sW[kq + 1][r] = wv.y;
        sW[kq + 2][r] = wv.z; sW[kq + 3][r] = wv.w;
        __syncthreads();
        #pragma unroll
        for (int k = 0; k < 16; k++) {
            float4 a  = *(const float4*)&sX[k][ty * 4];
            float4 w4 = *(const float4*)&sW[k][tx * 4];
            float av[4] = {a.x, a.y, a.z, a.w};
            float bv4[4] = {w4.x, w4.y, w4.z, w4.w};
            #pragma unroll
            for (int i = 0; i < 4; i++)
                #pragma unroll
                for (int j = 0; j < 4; j++)
                    acc[i][j] = fmaf(av[i], bv4[j], acc[i][j]);
        }
        __syncthreads();
    }

    #pragma unroll
    for (int i = 0; i < 4; i++) {
        int m = m0 + ty * 4 + i;
        int b = m >> 12, n = m & (Nseq - 1);
        #pragma unroll
        for (int j = 0; j < 4; j += 2) {
            int o = o0 + tx * 4 + j;
            int h = o >> 6, dd = o & 63;
            float v0 = (acc[i][j] + bias[o]) * oscale;
            float v1 = (acc[i][j + 1] + bias[o + 1]) * oscale;
            *(__half2*)&out[(((size_t)(b * Hh + h) * Nseq) + n) * Dh + dd] =
                __floats2half2_rn(v0, v1);
        }
    }
}

// ---------------------------------------------------------------------------
// Flash attention, fp16 m16n8k16 + ldmatrix. CTA = 4 warps, BM=64, BN=64.
// Q pre-scaled by 0.125*log2(e); softmax in exp2 domain; adj via bitmasks.
// ---------------------------------------------------------------------------
__global__ __launch_bounds__(128, 4) void flash_kernel()
{
    __shared__ __align__(16) __half sQP[64 * HPAD];   // Q, then P
    __shared__ __align__(16) __half sK[64 * HPAD];
    __shared__ __align__(16) __half sV[64 * HPAD];
    __shared__ unsigned sAdjB[128];

    int tid  = threadIdx.x;
    int lane = tid & 31;
    int warp = tid >> 5;
    int wrow0 = warp * 16;
    int q0 = blockIdx.x * 64;
    int h = blockIdx.y, b = blockIdx.z;

    const __half* Qg = g_q + (size_t)(b * Hh + h) * Nseq * Dh;
    const __half* Kg = g_k + (size_t)(b * Hh + h) * Nseq * Dh;
    const __half* Vg = g_v + (size_t)(b * Hh + h) * Nseq * Dh;

    // ---- stage Q (already scaled fp16) ----
    #pragma unroll
    for (int i = 0; i < 4; i++) {
        int fl = tid + 128 * i, r = fl >> 3, c8 = fl & 7;
        *(uint4*)&sQP[r * HPAD + c8 * 8] = *(const uint4*)&Qg[(q0 + r) * Dh + c8 * 8];
    }
    __syncthreads();

    // ---- Q A-fragments (held all kernel): 4 k-blocks x 4 regs ----
    unsigned qa[4][4];
    {
        int m = lane >> 3;
        int row = wrow0 + (m & 1) * 8 + (lane & 7);
        #pragma unroll
        for (int kb4 = 0; kb4 < 4; kb4++)
            ldsm4(qa[kb4], sa(&sQP[row * HPAD + (kb4 * 2 + (m >> 1)) * 8]));
    }

    float o[8][4];
    #pragma unroll
    for (int n = 0; n < 8; n++)
        #pragma unroll
        for (int j = 0; j < 4; j++) o[n][j] = 0.f;
    float mA = -1e30f, mB = -1e30f, lA = 0.f, lB = 0.f;
    int rA = wrow0 + (lane >> 2);

    for (int t = 0; t < Nseq / 64; t++) {
        int kb = t * 64;
        __syncthreads();   // prev-tile consumers done with sK/sV/sQP/sAdjB

        // ---- stage K, V (fp16 memcpy) + adj words ----
        #pragma unroll
        for (int i = 0; i < 4; i++) {
            int fl = tid + 128 * i, r = fl >> 3, c8 = fl & 7;
            *(uint4*)&sK[r * HPAD + c8 * 8] = *(const uint4*)&Kg[(kb + r) * Dh + c8 * 8];
            *(uint4*)&sV[r * HPAD + c8 * 8] = *(const uint4*)&Vg[(kb + r) * Dh + c8 * 8];
        }
        {
            int row = tid >> 1, half = tid & 1;
            sAdjB[tid] = g_adjb[(size_t)(b * Nseq + q0 + row) * (Nseq / 32) + t * 2 + half];
        }
        __syncthreads();

        // ---- S = Qs @ K^T ----
        float s[8][4];
        #pragma unroll
        for (int n = 0; n < 8; n++)
            #pragma unroll
            for (int j = 0; j < 4; j++) s[n][j] = 0.f;
        {
            int m = lane >> 3;
            int keyb = (m >> 1) * 8 + (lane & 7);
            int ch = m & 1;
            #pragma unroll
            for (int kb4 = 0; kb4 < 4; kb4++) {
                #pragma unroll
                for (int np = 0; np < 4; np++) {
                    unsigned bb[4];
                    ldsm4(bb, sa(&sK[(np * 16 + keyb) * HPAD + (kb4 * 2 + ch) * 8]));
                    mma16(s[np * 2],     qa[kb4], bb[0], bb[1]);
                    mma16(s[np * 2 + 1], qa[kb4], bb[2], bb[3]);
                }
            }
        }

        // ---- mask + online softmax (log2 domain) ----
        unsigned a0m = sAdjB[rA * 2], a1m = sAdjB[rA * 2 + 1];
        unsigned b0m = sAdjB[(rA + 8) * 2], b1m = sAdjB[(rA + 8) * 2 + 1];
        float mxA = -1e30f, mxB = -1e30f;
        #pragma unroll
        for (int n = 0; n < 8; n++) {
            int c = n * 8 + 2 * (lane & 3);
            int sh = c & 31;
            unsigned wA = (n < 4) ? a0m : a1m;
            unsigned wB = (n < 4) ? b0m : b1m;
            s[n][0] = ((wA >> sh) & 1u) ? s[n][0] : NEGV;
            s[n][1] = ((wA >> (sh + 1)) & 1u) ? s[n][1] : NEGV;
            s[n][2] = ((wB >> sh) & 1u) ? s[n][2] : NEGV;
            s[n][3] = ((wB >> (sh + 1)) & 1u) ? s[n][3] : NEGV;
            mxA = fmaxf(mxA, fmaxf(s[n][0], s[n][1]));
            mxB = fmaxf(mxB, fmaxf(s[n][2], s[n][3]));
        }
        mxA = fmaxf(mxA, __shfl_xor_sync(0xffffffffu, mxA, 1));
        mxA = fmaxf(mxA, __shfl_xor_sync(0xffffffffu, mxA, 2));
        mxB = fmaxf(mxB, __shfl_xor_sync(0xffffffffu, mxB, 1));
        mxB = fmaxf(mxB, __shfl_xor_sync(0xffffffffu, mxB, 2));

        float mnA = fmaxf(mA, mxA), mnB = fmaxf(mB, mxB);
        float alA = exp2f(mA - mnA), alB = exp2f(mB - mnB);
        mA = mnA; mB = mnB;

        float suA = 0.f, suB = 0.f;
        #pragma unroll
        for (int n = 0; n < 8; n++) {
            int c = n * 8 + 2 * (lane & 3);
            float p0 = exp2f(s[n][0] - mnA);
            float p1 = exp2f(s[n][1] - mnA);
            float p2 = exp2f(s[n][2] - mnB);
            float p3 = exp2f(s[n][3] - mnB);
            suA += p0 + p1; suB += p2 + p3;
            *(__half2*)&sQP[rA * HPAD + c]       = __floats2half2_rn(p0, p1);
            *(__half2*)&sQP[(rA + 8) * HPAD + c] = __floats2half2_rn(p2, p3);
        }
        suA += __shfl_xor_sync(0xffffffffu, suA, 1);
        suA += __shfl_xor_sync(0xffffffffu, suA, 2);
        suB += __shfl_xor_sync(0xffffffffu, suB, 1);
        suB += __shfl_xor_sync(0xffffffffu, suB, 2);
        lA = lA * alA + suA;
        lB = lB * alB + suB;
        #pragma unroll
        for (int n = 0; n < 8; n++) {
            o[n][0] *= alA; o[n][1] *= alA;
            o[n][2] *= alB; o[n][3] *= alB;
        }
        __syncwarp();   // per-warp P region visible

        // ---- O += P @ V ----
        {
            int m = lane >> 3;
            int prow = wrow0 + (m & 1) * 8 + (lane & 7);
            #pragma unroll
            for (int kk = 0; kk < 4; kk++) {
                unsigned pa[4];
                ldsm4(pa, sa(&sQP[prow * HPAD + (kk * 2 + (m >> 1)) * 8]));
                int vkey = kk * 16 + (m & 1) * 8 + (lane & 7);
                #pragma unroll
                for (int np = 0; np < 4; np++) {
                    unsigned vb[4];
                    ldsm4t(vb, sa(&sV[vkey * HPAD + (np * 2 + (m >> 1)) * 8]));
                    mma16(o[np * 2],     pa, vb[0], vb[1]);
                    mma16(o[np * 2 + 1], pa, vb[2], vb[3]);
                }
            }
        }
    }

    // ---- normalize + write [B,N,C] fp32 ----
    float ivA = 1.f / lA, ivB = 1.f / lB;
    int gr = b * Nseq + q0 + rA;
    #pragma unroll
    for (int n = 0; n < 8; n++) {
        int c = h * Dh + n * 8 + 2 * (lane & 3);
        float2 wa; wa.x = o[n][0] * ivA; wa.y = o[n][1] * ivA;
        *(float2*)&g_ao[(size_t)gr * Cdim + c] = wa;
        float2 wb; wb.x = o[n][2] * ivB; wb.y = o[n][3] * ivB;
        *(float2*)&g_ao[(size_t)(gr + 8) * Cdim + c] = wb;
    }
}

// ---------------------------------------------------------------------------
// Out-proj + bias + LayerNorm, fused (unchanged).
// ---------------------------------------------------------------------------
__global__ __launch_bounds__(256) void outln_kernel(const float* __restrict__ Wo,
                                                    const float* __restrict__ bo,
                                                    const float* __restrict__ gamma,
                                                    const float* __restrict__ beta,
                                                    float* __restrict__ out)
{
    __shared__ float sX[32][36];
    __shared__ float sW[32][260];
    int tid = threadIdx.x;
    int tx = tid & 31, ty = tid >> 5;
    int m0 = blockIdx.x * 32;
    float acc[4][8] = {};

    for (int k0 = 0; k0 < Cdim; k0 += 32) {
        {
            int r = tid >> 3, c4 = (tid & 7) * 4;
            *(float4*)&sX[r][c4] = *(const float4*)&g_ao[(m0 + r) * Cdim + k0 + c4];
        }
        #pragma unroll
        for (int w4 = 0; w4 < 8; w4++) {
            int fl = tid + 256 * w4;
            int o = fl >> 3, c4 = (fl & 7) * 4;
            float4 wv = *(const float4*)&Wo[o * Cdim + k0 + c4];
            sW[c4 + 0][o] = wv.x; sW[c4 + 1][o] = wv.y;
            sW[c4 + 2][o] = wv.z; sW[c4 + 3][o] = wv.w;
        }
        __syncthreads();
        #pragma unroll 8
        for (int k = 0; k < 32; k++) {
            float xv[4];
            #pragma unroll
            for (int i = 0; i < 4; i++) xv[i] = sX[ty * 4 + i][k];
            #pragma unroll
            for (int jj = 0; jj < 8; jj++) {
                float wv = sW[k][tx + 32 * jj];
                #pragma unroll
                for (int i = 0; i < 4; i++)
                    acc[i][jj] = fmaf(xv[i], wv, acc[i][jj]);
            }
        }
        __syncthreads();
    }

    #pragma unroll
    for (int i = 0; i < 4; i++) {
        float sum = 0.f, sq = 0.f;
        #pragma unroll
        for (int jj = 0; jj < 8; jj++) {
            float y = acc[i][jj] + bo[tx + 32 * jj];
            acc[i][jj] = y;
            sum += y; sq += y * y;
        }
        #pragma unroll
        for (int off = 16; off >= 1; off >>= 1) {
            sum += __shfl_xor_sync(0xffffffffu, sum, off);
            sq  += __shfl_xor_sync(0xffffffffu, sq, off);
        }
        float mu  = sum * (1.f / 256.f);
        float var = sq * (1.f / 256.f) - mu * mu;
        float rst = rsqrtf(var + EPSL);
        int row = m0 + ty * 4 + i;
        #pragma unroll
        for (int jj = 0; jj < 8; jj++) {
            int c = tx + 32 * jj;
            out[row * Cdim + c] = (acc[i][jj] - mu) * rst * gamma[c] + beta[c];
        }
    }
}

// ---------------------------------------------------------------------------
extern "C" void kernel_launch(void* const* d_in, const int* in_sizes, int n_in,
                              void* d_out, int out_size)
{
    const float* x     = (const float*)d_in[0];
    const int*   adj   = (const int*)  d_in[1];
    const float* Wq    = (const float*)d_in[2];
    const float* bq    = (const float*)d_in[3];
    const float* Wk    = (const float*)d_in[4];
    const float* bk    = (const float*)d_in[5];
    const float* Wv    = (const float*)d_in[6];
    const float* bv    = (const float*)d_in[7];
    const float* Wo    = (const float*)d_in[8];
    const float* bo    = (const float*)d_in[9];
    const float* gamma = (const float*)d_in[10];
    const float* beta  = (const float*)d_in[11];
    float* out = (float*)d_out;

    pack_adj_kernel<<<(Bsz * Nseq * Nseq) / 256, 256>>>(adj);

    dim3 pgrid(Cdim / 64, (Bsz * Nseq) / 64, 3);
    proj_kernel<<<pgrid, 256>>>(x, Wq, bq, Wk, bk, Wv, bv);

    dim3 fgrid(Nseq / 64, Hh, Bsz);
    flash_kernel<<<fgrid, 128>>>();

    outln_kernel<<<(Bsz * Nseq) / 32, 256>>>(Wo, bo, gamma, beta, out);
}

// round 9
// speedup vs baseline: 6.5527x; 1.2932x over previous
#include <cuda_runtime.h>
#include <cuda_fp16.h>

#define Bsz  2
#define Nseq 4096
#define Cdim 256
#define Hh   4
#define Dh   64
#define NEGV -1e9f
#define EPSL 1e-5f
#define HPAD 72   // halves per smem row (144B = 36 words = 4 mod 32 banks)

// Scratch (allocation-free rule: __device__ globals)
__device__ __half   g_xh[Bsz * Nseq * Cdim];
__device__ __half   g_q[Bsz * Hh * Nseq * Dh];
__device__ __half   g_k[Bsz * Hh * Nseq * Dh];
__device__ __half   g_v[Bsz * Hh * Nseq * Dh];
__device__ __half   g_aoh[Bsz * Nseq * Cdim];
__device__ unsigned g_adjb[Bsz * Nseq * (Nseq / 32)];

// ---------------------------------------------------------------------------
// helpers
// ---------------------------------------------------------------------------
__device__ __forceinline__ unsigned sa(const void* p)
{
    return (unsigned)__cvta_generic_to_shared(p);
}

__device__ __forceinline__ void ldsm4(unsigned* r, unsigned a)
{
    asm volatile("ldmatrix.sync.aligned.m8n8.x4.shared.b16 {%0,%1,%2,%3}, [%4];"
                 : "=r"(r[0]), "=r"(r[1]), "=r"(r[2]), "=r"(r[3]) : "r"(a));
}

__device__ __forceinline__ void ldsm4t(unsigned* r, unsigned a)
{
    asm volatile("ldmatrix.sync.aligned.m8n8.x4.trans.shared.b16 {%0,%1,%2,%3}, [%4];"
                 : "=r"(r[0]), "=r"(r[1]), "=r"(r[2]), "=r"(r[3]) : "r"(a));
}

__device__ __forceinline__ void mma16(float* d, const unsigned* a, unsigned b0, unsigned b1)
{
    asm volatile(
        "mma.sync.aligned.m16n8k16.row.col.f32.f16.f16.f32 "
        "{%0,%1,%2,%3}, {%4,%5,%6,%7}, {%8,%9}, {%0,%1,%2,%3};"
        : "+f"(d[0]), "+f"(d[1]), "+f"(d[2]), "+f"(d[3])
        : "r"(a[0]), "r"(a[1]), "r"(a[2]), "r"(a[3]), "r"(b0), "r"(b1));
}

// ---------------------------------------------------------------------------
// X fp32 -> fp16 pre-pass
// ---------------------------------------------------------------------------
__global__ __launch_bounds__(256) void x2h_kernel(const float* __restrict__ X)
{
    int i = (blockIdx.x * 256 + threadIdx.x) * 4;
    float4 v = *(const float4*)&X[i];
    *(__half2*)&g_xh[i]     = __floats2half2_rn(v.x, v.y);
    *(__half2*)&g_xh[i + 2] = __floats2half2_rn(v.z, v.w);
}

// ---------------------------------------------------------------------------
// adj -> bitmask pre-pass
// ---------------------------------------------------------------------------
__global__ __launch_bounds__(256) void pack_adj_kernel(const int* __restrict__ adj)
{
    int gid = blockIdx.x * 256 + threadIdx.x;
    unsigned m = __ballot_sync(0xffffffffu, adj[gid] != 0);
    if ((threadIdx.x & 31) == 0) g_adjb[gid >> 5] = m;
}

// ---------------------------------------------------------------------------
// QKV projection, fp16 mma. BM=128, BN=64, BK=64, 4 warps.
// blockIdx.z selects q/k/v; Q pre-scaled by 0.125*log2(e). Out: [B,H,N,D] fp16.
// ---------------------------------------------------------------------------
__global__ __launch_bounds__(128) void projmma_kernel(const float* __restrict__ Wq,
                                                      const float* __restrict__ bq,
                                                      const float* __restrict__ Wk,
                                                      const float* __restrict__ bk,
                                                      const float* __restrict__ Wv,
                                                      const float* __restrict__ bv)
{
    int which = blockIdx.z;
    const float* W    = (which == 0) ? Wq : (which == 1) ? Wk : Wv;
    const float* bias = (which == 0) ? bq : (which == 1) ? bk : bv;
    __half* out       = (which == 0) ? g_q : (which == 1) ? g_k : g_v;
    float oscale      = (which == 0) ? 0.125f * 1.44269504089f : 1.f;

    __shared__ __align__(16) __half sX[128 * HPAD];
    __shared__ __align__(16) __half sW[64 * HPAD];

    int tid = threadIdx.x, lane = tid & 31, warp = tid >> 5;
    int m = lane >> 3;
    int m0 = blockIdx.y * 128, o0 = blockIdx.x * 64;
    float acc[2][8][4] = {};

    for (int k0 = 0; k0 < Cdim; k0 += 64) {
        __syncthreads();
        #pragma unroll
        for (int i = 0; i < 8; i++) {          // X tile 128x64 fp16
            int fl = tid + 128 * i, r = fl >> 3, c8 = fl & 7;
            *(uint4*)&sX[r * HPAD + c8 * 8] =
                *(const uint4*)&g_xh[(size_t)(m0 + r) * Cdim + k0 + c8 * 8];
        }
        #pragma unroll
        for (int i = 0; i < 8; i++) {          // W tile 64x64 fp32 -> fp16
            int fl = tid + 128 * i, r = fl >> 4, c4 = (fl & 15) * 4;
            float4 w = *(const float4*)&W[(size_t)(o0 + r) * Cdim + k0 + c4];
            *(__half2*)&sW[r * HPAD + c4]     = __floats2half2_rn(w.x, w.y);
            *(__half2*)&sW[r * HPAD + c4 + 2] = __floats2half2_rn(w.z, w.w);
        }
        __syncthreads();

        #pragma unroll
        for (int ks = 0; ks < 4; ks++) {
            unsigned qa0[4], qa1[4];
            int arow = warp * 32 + (m & 1) * 8 + (lane & 7);
            ldsm4(qa0, sa(&sX[arow * HPAD + (ks * 2 + (m >> 1)) * 8]));
            ldsm4(qa1, sa(&sX[(arow + 16) * HPAD + (ks * 2 + (m >> 1)) * 8]));
            int keyb = (m >> 1) * 8 + (lane & 7);
            int ch = m & 1;
            #pragma unroll
            for (int np = 0; np < 4; np++) {
                unsigned bb[4];
                ldsm4(bb, sa(&sW[(np * 16 + keyb) * HPAD + (ks * 2 + ch) * 8]));
                mma16(acc[0][np * 2],     qa0, bb[0], bb[1]);
                mma16(acc[0][np * 2 + 1], qa0, bb[2], bb[3]);
                mma16(acc[1][np * 2],     qa1, bb[0], bb[1]);
                mma16(acc[1][np * 2 + 1], qa1, bb[2], bb[3]);
            }
        }
    }

    int h = o0 >> 6;   // BN=64 == Dh: head fixed per CTA
    #pragma unroll
    for (int mf = 0; mf < 2; mf++) {
        int r0 = m0 + warp * 32 + mf * 16 + (lane >> 2);
        #pragma unroll
        for (int f = 0; f < 8; f++) {
            int dd = (f >> 1) * 16 + (f & 1) * 8 + 2 * (lane & 3);
            float b0v = bias[o0 + dd], b1v = bias[o0 + dd + 1];
            {
                int n = r0 & (Nseq - 1), b = r0 >> 12;
                *(__half2*)&out[((size_t)(b * Hh + h) * Nseq + n) * Dh + dd] =
                    __floats2half2_rn((acc[mf][f][0] + b0v) * oscale,
                                      (acc[mf][f][1] + b1v) * oscale);
            }
            {
                int r1 = r0 + 8;
                int n = r1 & (Nseq - 1), b = r1 >> 12;
                *(__half2*)&out[((size_t)(b * Hh + h) * Nseq + n) * Dh + dd] =
                    __floats2half2_rn((acc[mf][f][2] + b0v) * oscale,
                                      (acc[mf][f][3] + b1v) * oscale);
            }
        }
    }
}

// ---------------------------------------------------------------------------
// Flash attention, fp16 m16n8k16 + ldmatrix (unchanged core; fp16 output).
// ---------------------------------------------------------------------------
__global__ __launch_bounds__(128, 4) void flash_kernel()
{
    __shared__ __align__(16) __half sQP[64 * HPAD];   // Q, then P
    __shared__ __align__(16) __half sK[64 * HPAD];
    __shared__ __align__(16) __half sV[64 * HPAD];
    __shared__ unsigned sAdjB[128];

    int tid  = threadIdx.x;
    int lane = tid & 31;
    int warp = tid >> 5;
    int wrow0 = warp * 16;
    int q0 = blockIdx.x * 64;
    int h = blockIdx.y, b = blockIdx.z;

    const __half* Qg = g_q + (size_t)(b * Hh + h) * Nseq * Dh;
    const __half* Kg = g_k + (size_t)(b * Hh + h) * Nseq * Dh;
    const __half* Vg = g_v + (size_t)(b * Hh + h) * Nseq * Dh;

    #pragma unroll
    for (int i = 0; i < 4; i++) {
        int fl = tid + 128 * i, r = fl >> 3, c8 = fl & 7;
        *(uint4*)&sQP[r * HPAD + c8 * 8] = *(const uint4*)&Qg[(q0 + r) * Dh + c8 * 8];
    }
    __syncthreads();

    unsigned qa[4][4];
    {
        int m = lane >> 3;
        int row = wrow0 + (m & 1) * 8 + (lane & 7);
        #pragma unroll
        for (int kb4 = 0; kb4 < 4; kb4++)
            ldsm4(qa[kb4], sa(&sQP[row * HPAD + (kb4 * 2 + (m >> 1)) * 8]));
    }

    float o[8][4];
    #pragma unroll
    for (int n = 0; n < 8; n++)
        #pragma unroll
        for (int j = 0; j < 4; j++) o[n][j] = 0.f;
    float mA = -1e30f, mB = -1e30f, lA = 0.f, lB = 0.f;
    int rA = wrow0 + (lane >> 2);

    for (int t = 0; t < Nseq / 64; t++) {
        int kb = t * 64;
        __syncthreads();

        #pragma unroll
        for (int i = 0; i < 4; i++) {
            int fl = tid + 128 * i, r = fl >> 3, c8 = fl & 7;
            *(uint4*)&sK[r * HPAD + c8 * 8] = *(const uint4*)&Kg[(kb + r) * Dh + c8 * 8];
            *(uint4*)&sV[r * HPAD + c8 * 8] = *(const uint4*)&Vg[(kb + r) * Dh + c8 * 8];
        }
        {
            int row = tid >> 1, half = tid & 1;
            sAdjB[tid] = g_adjb[(size_t)(b * Nseq + q0 + row) * (Nseq / 32) + t * 2 + half];
        }
        __syncthreads();

        float s[8][4];
        #pragma unroll
        for (int n = 0; n < 8; n++)
            #pragma unroll
            for (int j = 0; j < 4; j++) s[n][j] = 0.f;
        {
            int m = lane >> 3;
            int keyb = (m >> 1) * 8 + (lane & 7);
            int ch = m & 1;
            #pragma unroll
            for (int kb4 = 0; kb4 < 4; kb4++) {
                #pragma unroll
                for (int np = 0; np < 4; np++) {
                    unsigned bb[4];
                    ldsm4(bb, sa(&sK[(np * 16 + keyb) * HPAD + (kb4 * 2 + ch) * 8]));
                    mma16(s[np * 2],     qa[kb4], bb[0], bb[1]);
                    mma16(s[np * 2 + 1], qa[kb4], bb[2], bb[3]);
                }
            }
        }

        unsigned a0m = sAdjB[rA * 2], a1m = sAdjB[rA * 2 + 1];
        unsigned b0m = sAdjB[(rA + 8) * 2], b1m = sAdjB[(rA + 8) * 2 + 1];
        float mxA = -1e30f, mxB = -1e30f;
        #pragma unroll
        for (int n = 0; n < 8; n++) {
            int c = n * 8 + 2 * (lane & 3);
            int sh = c & 31;
            unsigned wA = (n < 4) ? a0m : a1m;
            unsigned wB = (n < 4) ? b0m : b1m;
            s[n][0] = ((wA >> sh) & 1u) ? s[n][0] : NEGV;
            s[n][1] = ((wA >> (sh + 1)) & 1u) ? s[n][1] : NEGV;
            s[n][2] = ((wB >> sh) & 1u) ? s[n][2] : NEGV;
            s[n][3] = ((wB >> (sh + 1)) & 1u) ? s[n][3] : NEGV;
            mxA = fmaxf(mxA, fmaxf(s[n][0], s[n][1]));
            mxB = fmaxf(mxB, fmaxf(s[n][2], s[n][3]));
        }
        mxA = fmaxf(mxA, __shfl_xor_sync(0xffffffffu, mxA, 1));
        mxA = fmaxf(mxA, __shfl_xor_sync(0xffffffffu, mxA, 2));
        mxB = fmaxf(mxB, __shfl_xor_sync(0xffffffffu, mxB, 1));
        mxB = fmaxf(mxB, __shfl_xor_sync(0xffffffffu, mxB, 2));

        float mnA = fmaxf(mA, mxA), mnB = fmaxf(mB, mxB);
        float alA = exp2f(mA - mnA), alB = exp2f(mB - mnB);
        mA = mnA; mB = mnB;

        float suA = 0.f, suB = 0.f;
        #pragma unroll
        for (int n = 0; n < 8; n++) {
            int c = n * 8 + 2 * (lane & 3);
            float p0 = exp2f(s[n][0] - mnA);
            float p1 = exp2f(s[n][1] - mnA);
            float p2 = exp2f(s[n][2] - mnB);
            float p3 = exp2f(s[n][3] - mnB);
            suA += p0 + p1; suB += p2 + p3;
            *(__half2*)&sQP[rA * HPAD + c]       = __floats2half2_rn(p0, p1);
            *(__half2*)&sQP[(rA + 8) * HPAD + c] = __floats2half2_rn(p2, p3);
        }
        suA += __shfl_xor_sync(0xffffffffu, suA, 1);
        suA += __shfl_xor_sync(0xffffffffu, suA, 2);
        suB += __shfl_xor_sync(0xffffffffu, suB, 1);
        suB += __shfl_xor_sync(0xffffffffu, suB, 2);
        lA = lA * alA + suA;
        lB = lB * alB + suB;
        #pragma unroll
        for (int n = 0; n < 8; n++) {
            o[n][0] *= alA; o[n][1] *= alA;
            o[n][2] *= alB; o[n][3] *= alB;
        }
        __syncwarp();

        {
            int m = lane >> 3;
            int prow = wrow0 + (m & 1) * 8 + (lane & 7);
            #pragma unroll
            for (int kk = 0; kk < 4; kk++) {
                unsigned pa[4];
                ldsm4(pa, sa(&sQP[prow * HPAD + (kk * 2 + (m >> 1)) * 8]));
                int vkey = kk * 16 + (m & 1) * 8 + (lane & 7);
                #pragma unroll
                for (int np = 0; np < 4; np++) {
                    unsigned vb[4];
                    ldsm4t(vb, sa(&sV[vkey * HPAD + (np * 2 + (m >> 1)) * 8]));
                    mma16(o[np * 2],     pa, vb[0], vb[1]);
                    mma16(o[np * 2 + 1], pa, vb[2], vb[3]);
                }
            }
        }
    }

    float ivA = 1.f / lA, ivB = 1.f / lB;
    int gr = b * Nseq + q0 + rA;
    #pragma unroll
    for (int n = 0; n < 8; n++) {
        int c = h * Dh + n * 8 + 2 * (lane & 3);
        *(__half2*)&g_aoh[(size_t)gr * Cdim + c] =
            __floats2half2_rn(o[n][0] * ivA, o[n][1] * ivA);
        *(__half2*)&g_aoh[(size_t)(gr + 8) * Cdim + c] =
            __floats2half2_rn(o[n][2] * ivB, o[n][3] * ivB);
    }
}

// ---------------------------------------------------------------------------
// Out-proj + bias + LayerNorm, fp16 mma. BM=64, BN=256 (full row), 8 warps.
// Warp grid 4m x 2n; LN stats: quad shuffles + 1KB smem exchange across n-warps.
// ---------------------------------------------------------------------------
__global__ __launch_bounds__(256) void outlnmma_kernel(const float* __restrict__ Wo,
                                                       const float* __restrict__ bo,
                                                       const float* __restrict__ gamma,
                                                       const float* __restrict__ beta,
                                                       float* __restrict__ out)
{
    __shared__ __align__(16) __half sA[64 * HPAD];
    __shared__ __align__(16) __half sW[256 * HPAD];
    __shared__ float sStat[2][64][2];

    int tid = threadIdx.x, lane = tid & 31, warp = tid >> 5;
    int wm = warp & 3, wn = warp >> 2;
    int m = lane >> 3;
    int m0 = blockIdx.x * 64;
    float acc[16][4] = {};

    for (int k0 = 0; k0 < Cdim; k0 += 64) {
        __syncthreads();
        #pragma unroll
        for (int i = 0; i < 2; i++) {          // A tile 64x64 fp16
            int fl = tid + 256 * i, r = fl >> 3, c8 = fl & 7;
            *(uint4*)&sA[r * HPAD + c8 * 8] =
                *(const uint4*)&g_aoh[(size_t)(m0 + r) * Cdim + k0 + c8 * 8];
        }
        #pragma unroll
        for (int i = 0; i < 16; i++) {         // W tile 256x64 fp32 -> fp16
            int fl = tid + 256 * i, r = fl >> 4, c4 = (fl & 15) * 4;
            float4 w = *(const float4*)&Wo[(size_t)r * Cdim + k0 + c4];
            *(__half2*)&sW[r * HPAD + c4]     = __floats2half2_rn(w.x, w.y);
            *(__half2*)&sW[r * HPAD + c4 + 2] = __floats2half2_rn(w.z, w.w);
        }
        __syncthreads();

        #pragma unroll
        for (int ks = 0; ks < 4; ks++) {
            unsigned qa[4];
            ldsm4(qa, sa(&sA[(wm * 16 + (m & 1) * 8 + (lane & 7)) * HPAD
                             + (ks * 2 + (m >> 1)) * 8]));
            int keyb = (m >> 1) * 8 + (lane & 7);
            int ch = m & 1;
            #pragma unroll
            for (int np = 0; np < 8; np++) {
                unsigned bb[4];
                ldsm4(bb, sa(&sW[(wn * 128 + np * 16 + keyb) * HPAD
                                 + (ks * 2 + ch) * 8]));
                mma16(acc[np * 2],     qa, bb[0], bb[1]);
                mma16(acc[np * 2 + 1], qa, bb[2], bb[3]);
            }
        }
    }

    // bias + per-row partial stats
    float suA = 0.f, sqA = 0.f, suB = 0.f, sqB = 0.f;
    #pragma unroll
    for (int f = 0; f < 16; f++) {
        int c = wn * 128 + (f >> 1) * 16 + (f & 1) * 8 + 2 * (lane & 3);
        float b0 = bo[c], b1 = bo[c + 1];
        acc[f][0] += b0; acc[f][1] += b1;
        acc[f][2] += b0; acc[f][3] += b1;
        suA += acc[f][0] + acc[f][1];
        sqA += acc[f][0] * acc[f][0] + acc[f][1] * acc[f][1];
        suB += acc[f][2] + acc[f][3];
        sqB += acc[f][2] * acc[f][2] + acc[f][3] * acc[f][3];
    }
    suA += __shfl_xor_sync(0xffffffffu, suA, 1);
    suA += __shfl_xor_sync(0xffffffffu, suA, 2);
    sqA += __shfl_xor_sync(0xffffffffu, sqA, 1);
    sqA += __shfl_xor_sync(0xffffffffu, sqA, 2);
    suB += __shfl_xor_sync(0xffffffffu, suB, 1);
    suB += __shfl_xor_sync(0xffffffffu, suB, 2);
    sqB += __shfl_xor_sync(0xffffffffu, sqB, 1);
    sqB += __shfl_xor_sync(0xffffffffu, sqB, 2);

    int rA = wm * 16 + (lane >> 2);
    if ((lane & 3) == 0) {
        sStat[wn][rA][0] = suA;     sStat[wn][rA][1] = sqA;
        sStat[wn][rA + 8][0] = suB; sStat[wn][rA + 8][1] = sqB;
    }
    __syncthreads();

    float sA2 = sStat[0][rA][0] + sStat[1][rA][0];
    float qA2 = sStat[0][rA][1] + sStat[1][rA][1];
    float sB2 = sStat[0][rA + 8][0] + sStat[1][rA + 8][0];
    float qB2 = sStat[0][rA + 8][1] + sStat[1][rA + 8][1];
    float muA = sA2 * (1.f / 256.f);
    float rsA = rsqrtf(qA2 * (1.f / 256.f) - muA * muA + EPSL);
    float muB = sB2 * (1.f / 256.f);
    float rsB = rsqrtf(qB2 * (1.f / 256.f) - muB * muB + EPSL);

    size_t rowA = (size_t)(m0 + rA) * Cdim;
    size_t rowB = (size_t)(m0 + rA + 8) * Cdim;
    #pragma unroll
    for (int f = 0; f < 16; f++) {
        int c = wn * 128 + (f >> 1) * 16 + (f & 1) * 8 + 2 * (lane & 3);
        float g0 = gamma[c], g1 = gamma[c + 1];
        float be0 = beta[c], be1 = beta[c + 1];
        float2 wa;
        wa.x = (acc[f][0] - muA) * rsA * g0 + be0;
        wa.y = (acc[f][1] - muA) * rsA * g1 + be1;
        *(float2*)&out[rowA + c] = wa;
        float2 wb;
        wb.x = (acc[f][2] - muB) * rsB * g0 + be0;
        wb.y = (acc[f][3] - muB) * rsB * g1 + be1;
        *(float2*)&out[rowB + c] = wb;
    }
}

// ---------------------------------------------------------------------------
extern "C" void kernel_launch(void* const* d_in, const int* in_sizes, int n_in,
                              void* d_out, int out_size)
{
    const float* x     = (const float*)d_in[0];
    const int*   adj   = (const int*)  d_in[1];
    const float* Wq    = (const float*)d_in[2];
    const float* bq    = (const float*)d_in[3];
    const float* Wk    = (const float*)d_in[4];
    const float* bk    = (const float*)d_in[5];
    const float* Wv    = (const float*)d_in[6];
    const float* bv    = (const float*)d_in[7];
    const float* Wo    = (const float*)d_in[8];
    const float* bo    = (const float*)d_in[9];
    const float* gamma = (const float*)d_in[10];
    const float* beta  = (const float*)d_in[11];
    float* out = (float*)d_out;

    x2h_kernel<<<(Bsz * Nseq * Cdim) / (256 * 4), 256>>>(x);
    pack_adj_kernel<<<(Bsz * Nseq * Nseq) / 256, 256>>>(adj);

    dim3 pgrid(Cdim / 64, (Bsz * Nseq) / 128, 3);
    projmma_kernel<<<pgrid, 128>>>(Wq, bq, Wk, bk, Wv, bv);

    dim3 fgrid(Nseq / 64, Hh, Bsz);
    flash_kernel<<<fgrid, 128>>>();

    outlnmma_kernel<<<(Bsz * Nseq) / 64, 256>>>(Wo, bo, gamma, beta, out);
}

// round 10
// speedup vs baseline: 6.6289x; 1.0116x over previous
#include <cuda_runtime.h>
#include <cuda_fp16.h>

#define Bsz  2
#define Nseq 4096
#define Cdim 256
#define Hh   4
#define Dh   64
#define NEGV -1e9f
#define EPSL 1e-5f
#define HPAD 72   // halves per smem row (144B = 36 words = 4 mod 32 banks)

// Scratch (allocation-free rule: __device__ globals)
__device__ __half   g_xh[Bsz * Nseq * Cdim];
__device__ __half   g_q[Bsz * Hh * Nseq * Dh];
__device__ __half   g_k[Bsz * Hh * Nseq * Dh];
__device__ __half   g_v[Bsz * Hh * Nseq * Dh];
__device__ __half   g_aoh[Bsz * Nseq * Cdim];
__device__ unsigned g_adjb[Bsz * Nseq * (Nseq / 32)];

// ---------------------------------------------------------------------------
// helpers
// ---------------------------------------------------------------------------
__device__ __forceinline__ unsigned sa(const void* p)
{
    return (unsigned)__cvta_generic_to_shared(p);
}

__device__ __forceinline__ void ldsm4(unsigned* r, unsigned a)
{
    asm volatile("ldmatrix.sync.aligned.m8n8.x4.shared.b16 {%0,%1,%2,%3}, [%4];"
                 : "=r"(r[0]), "=r"(r[1]), "=r"(r[2]), "=r"(r[3]) : "r"(a));
}

__device__ __forceinline__ void ldsm4t(unsigned* r, unsigned a)
{
    asm volatile("ldmatrix.sync.aligned.m8n8.x4.trans.shared.b16 {%0,%1,%2,%3}, [%4];"
                 : "=r"(r[0]), "=r"(r[1]), "=r"(r[2]), "=r"(r[3]) : "r"(a));
}

__device__ __forceinline__ void mma16(float* d, const unsigned* a, unsigned b0, unsigned b1)
{
    asm volatile(
        "mma.sync.aligned.m16n8k16.row.col.f32.f16.f16.f32 "
        "{%0,%1,%2,%3}, {%4,%5,%6,%7}, {%8,%9}, {%0,%1,%2,%3};"
        : "+f"(d[0]), "+f"(d[1]), "+f"(d[2]), "+f"(d[3])
        : "r"(a[0]), "r"(a[1]), "r"(a[2]), "r"(a[3]), "r"(b0), "r"(b1));
}

__device__ __forceinline__ void cpa16(unsigned dst, const void* src)
{
    asm volatile("cp.async.cg.shared.global [%0], [%1], 16;" :: "r"(dst), "l"(src));
}

__device__ __forceinline__ void cpa4(unsigned dst, const void* src)
{
    asm volatile("cp.async.ca.shared.global [%0], [%1], 4;" :: "r"(dst), "l"(src));
}

__device__ __forceinline__ void cp_commit()
{
    asm volatile("cp.async.commit_group;");
}

template <int N>
__device__ __forceinline__ void cp_wait()
{
    asm volatile("cp.async.wait_group %0;" :: "n"(N));
}

__device__ __forceinline__ unsigned h2pack(float a, float b)
{
    __half2 h = __floats2half2_rn(a, b);
    return *(unsigned*)&h;
}

// ---------------------------------------------------------------------------
// X fp32 -> fp16 pre-pass
// ---------------------------------------------------------------------------
__global__ __launch_bounds__(256) void x2h_kernel(const float* __restrict__ X)
{
    int i = (blockIdx.x * 256 + threadIdx.x) * 4;
    float4 v = *(const float4*)&X[i];
    *(__half2*)&g_xh[i]     = __floats2half2_rn(v.x, v.y);
    *(__half2*)&g_xh[i + 2] = __floats2half2_rn(v.z, v.w);
}

// ---------------------------------------------------------------------------
// adj -> bitmask pre-pass
// ---------------------------------------------------------------------------
__global__ __launch_bounds__(256) void pack_adj_kernel(const int* __restrict__ adj)
{
    int gid = blockIdx.x * 256 + threadIdx.x;
    unsigned m = __ballot_sync(0xffffffffu, adj[gid] != 0);
    if ((threadIdx.x & 31) == 0) g_adjb[gid >> 5] = m;
}

// ---------------------------------------------------------------------------
// QKV projection, fp16 mma. BM=128, BN=64, BK=64, 4 warps. (unchanged)
// ---------------------------------------------------------------------------
__global__ __launch_bounds__(128) void projmma_kernel(const float* __restrict__ Wq,
                                                      const float* __restrict__ bq,
                                                      const float* __restrict__ Wk,
                                                      const float* __restrict__ bk,
                                                      const float* __restrict__ Wv,
                                                      const float* __restrict__ bv)
{
    int which = blockIdx.z;
    const float* W    = (which == 0) ? Wq : (which == 1) ? Wk : Wv;
    const float* bias = (which == 0) ? bq : (which == 1) ? bk : bv;
    __half* out       = (which == 0) ? g_q : (which == 1) ? g_k : g_v;
    float oscale      = (which == 0) ? 0.125f * 1.44269504089f : 1.f;

    __shared__ __align__(16) __half sX[128 * HPAD];
    __shared__ __align__(16) __half sW[64 * HPAD];

    int tid = threadIdx.x, lane = tid & 31, warp = tid >> 5;
    int m = lane >> 3;
    int m0 = blockIdx.y * 128, o0 = blockIdx.x * 64;
    float acc[2][8][4] = {};

    for (int k0 = 0; k0 < Cdim; k0 += 64) {
        __syncthreads();
        #pragma unroll
        for (int i = 0; i < 8; i++) {
            int fl = tid + 128 * i, r = fl >> 3, c8 = fl & 7;
            *(uint4*)&sX[r * HPAD + c8 * 8] =
                *(const uint4*)&g_xh[(size_t)(m0 + r) * Cdim + k0 + c8 * 8];
        }
        #pragma unroll
        for (int i = 0; i < 8; i++) {
            int fl = tid + 128 * i, r = fl >> 4, c4 = (fl & 15) * 4;
            float4 w = *(const float4*)&W[(size_t)(o0 + r) * Cdim + k0 + c4];
            *(__half2*)&sW[r * HPAD + c4]     = __floats2half2_rn(w.x, w.y);
            *(__half2*)&sW[r * HPAD + c4 + 2] = __floats2half2_rn(w.z, w.w);
        }
        __syncthreads();

        #pragma unroll
        for (int ks = 0; ks < 4; ks++) {
            unsigned qa0[4], qa1[4];
            int arow = warp * 32 + (m & 1) * 8 + (lane & 7);
            ldsm4(qa0, sa(&sX[arow * HPAD + (ks * 2 + (m >> 1)) * 8]));
            ldsm4(qa1, sa(&sX[(arow + 16) * HPAD + (ks * 2 + (m >> 1)) * 8]));
            int keyb = (m >> 1) * 8 + (lane & 7);
            int ch = m & 1;
            #pragma unroll
            for (int np = 0; np < 4; np++) {
                unsigned bb[4];
                ldsm4(bb, sa(&sW[(np * 16 + keyb) * HPAD + (ks * 2 + ch) * 8]));
                mma16(acc[0][np * 2],     qa0, bb[0], bb[1]);
                mma16(acc[0][np * 2 + 1], qa0, bb[2], bb[3]);
                mma16(acc[1][np * 2],     qa1, bb[0], bb[1]);
                mma16(acc[1][np * 2 + 1], qa1, bb[2], bb[3]);
            }
        }
    }

    int h = o0 >> 6;
    #pragma unroll
    for (int mf = 0; mf < 2; mf++) {
        int r0 = m0 + warp * 32 + mf * 16 + (lane >> 2);
        #pragma unroll
        for (int f = 0; f < 8; f++) {
            int dd = (f >> 1) * 16 + (f & 1) * 8 + 2 * (lane & 3);
            float b0v = bias[o0 + dd], b1v = bias[o0 + dd + 1];
            {
                int n = r0 & (Nseq - 1), b = r0 >> 12;
                *(__half2*)&out[((size_t)(b * Hh + h) * Nseq + n) * Dh + dd] =
                    __floats2half2_rn((acc[mf][f][0] + b0v) * oscale,
                                      (acc[mf][f][1] + b1v) * oscale);
            }
            {
                int r1 = r0 + 8;
                int n = r1 & (Nseq - 1), b = r1 >> 12;
                *(__half2*)&out[((size_t)(b * Hh + h) * Nseq + n) * Dh + dd] =
                    __floats2half2_rn((acc[mf][f][2] + b0v) * oscale,
                                      (acc[mf][f][3] + b1v) * oscale);
            }
        }
    }
}

// ---------------------------------------------------------------------------
// Flash attention: fp16 mma, register-resident P, cp.async double buffering.
// CTA = 4 warps, BM=64, BN=64. Softmax in exp2 domain; adj via bitmasks.
// ---------------------------------------------------------------------------
__global__ __launch_bounds__(128, 4) void flash_kernel()
{
    __shared__ __align__(16) __half sQ[64 * HPAD];
    __shared__ __align__(16) __half sK[2][64 * HPAD];
    __shared__ __align__(16) __half sV[2][64 * HPAD];
    __shared__ unsigned sAdjB[2][128];

    int tid  = threadIdx.x;
    int lane = tid & 31;
    int warp = tid >> 5;
    int wrow0 = warp * 16;
    int q0 = blockIdx.x * 64;
    int h = blockIdx.y, b = blockIdx.z;

    const __half* Qg = g_q + (size_t)(b * Hh + h) * Nseq * Dh;
    const __half* Kg = g_k + (size_t)(b * Hh + h) * Nseq * Dh;
    const __half* Vg = g_v + (size_t)(b * Hh + h) * Nseq * Dh;
    const unsigned* Ag = g_adjb + (size_t)(b * Nseq + q0 + (tid >> 1)) * (Nseq / 32)
                               + (tid & 1);

    int srow = tid >> 3, scol = (tid & 7) * 8;          // staging coords

    // ---- issue stage 0 K/V/adj ----
    #pragma unroll
    for (int i = 0; i < 4; i++) {
        int r = srow + 16 * i;
        cpa16(sa(&sK[0][r * HPAD + scol]), &Kg[(size_t)r * Dh + scol]);
        cpa16(sa(&sV[0][r * HPAD + scol]), &Vg[(size_t)r * Dh + scol]);
    }
    cpa4(sa(&sAdjB[0][tid]), Ag);
    cp_commit();

    // ---- stage Q (plain loads, overlap with cp.async) ----
    #pragma unroll
    for (int i = 0; i < 4; i++) {
        int r = srow + 16 * i;
        *(uint4*)&sQ[r * HPAD + scol] = *(const uint4*)&Qg[(size_t)(q0 + r) * Dh + scol];
    }
    __syncthreads();

    // ---- Q A-fragments (held all kernel) ----
    unsigned qa[4][4];
    {
        int m = lane >> 3;
        int row = wrow0 + (m & 1) * 8 + (lane & 7);
        #pragma unroll
        for (int kb4 = 0; kb4 < 4; kb4++)
            ldsm4(qa[kb4], sa(&sQ[row * HPAD + (kb4 * 2 + (m >> 1)) * 8]));
    }

    float o[8][4];
    #pragma unroll
    for (int n = 0; n < 8; n++)
        #pragma unroll
        for (int j = 0; j < 4; j++) o[n][j] = 0.f;
    float mA = -1e30f, mB = -1e30f, lA = 0.f, lB = 0.f;
    int rA = wrow0 + (lane >> 2);

    const int NT = Nseq / 64;
    for (int t = 0; t < NT; t++) {
        int buf = t & 1;

        // issue t+1 into the other buffer (freed by the trailing sync of t-1)
        if (t + 1 < NT) {
            int nb = buf ^ 1;
            size_t kb1 = (size_t)(t + 1) * 64;
            #pragma unroll
            for (int i = 0; i < 4; i++) {
                int r = srow + 16 * i;
                cpa16(sa(&sK[nb][r * HPAD + scol]), &Kg[(kb1 + r) * Dh + scol]);
                cpa16(sa(&sV[nb][r * HPAD + scol]), &Vg[(kb1 + r) * Dh + scol]);
            }
            cpa4(sa(&sAdjB[nb][tid]), Ag + (t + 1) * 2);
            cp_commit();
            cp_wait<1>();
        } else {
            cp_wait<0>();
        }
        __syncthreads();

        // ---- S = Qs @ K^T ----
        float s[8][4];
        #pragma unroll
        for (int n = 0; n < 8; n++)
            #pragma unroll
            for (int j = 0; j < 4; j++) s[n][j] = 0.f;
        {
            int m = lane >> 3;
            int keyb = (m >> 1) * 8 + (lane & 7);
            int ch = m & 1;
            #pragma unroll
            for (int kb4 = 0; kb4 < 4; kb4++) {
                #pragma unroll
                for (int np = 0; np < 4; np++) {
                    unsigned bb[4];
                    ldsm4(bb, sa(&sK[buf][(np * 16 + keyb) * HPAD + (kb4 * 2 + ch) * 8]));
                    mma16(s[np * 2],     qa[kb4], bb[0], bb[1]);
                    mma16(s[np * 2 + 1], qa[kb4], bb[2], bb[3]);
                }
            }
        }

        // ---- mask + online softmax (log2 domain), P packed to registers ----
        unsigned a0m = sAdjB[buf][rA * 2], a1m = sAdjB[buf][rA * 2 + 1];
        unsigned b0m = sAdjB[buf][(rA + 8) * 2], b1m = sAdjB[buf][(rA + 8) * 2 + 1];
        float mxA = -1e30f, mxB = -1e30f;
        #pragma unroll
        for (int n = 0; n < 8; n++) {
            int sh = (n * 8 + 2 * (lane & 3)) & 31;
            unsigned wA = (n < 4) ? a0m : a1m;
            unsigned wB = (n < 4) ? b0m : b1m;
            s[n][0] = ((wA >> sh) & 1u) ? s[n][0] : NEGV;
            s[n][1] = ((wA >> (sh + 1)) & 1u) ? s[n][1] : NEGV;
            s[n][2] = ((wB >> sh) & 1u) ? s[n][2] : NEGV;
            s[n][3] = ((wB >> (sh + 1)) & 1u) ? s[n][3] : NEGV;
            mxA = fmaxf(mxA, fmaxf(s[n][0], s[n][1]));
            mxB = fmaxf(mxB, fmaxf(s[n][2], s[n][3]));
        }
        mxA = fmaxf(mxA, __shfl_xor_sync(0xffffffffu, mxA, 1));
        mxA = fmaxf(mxA, __shfl_xor_sync(0xffffffffu, mxA, 2));
        mxB = fmaxf(mxB, __shfl_xor_sync(0xffffffffu, mxB, 1));
        mxB = fmaxf(mxB, __shfl_xor_sync(0xffffffffu, mxB, 2));

        float mnA = fmaxf(mA, mxA), mnB = fmaxf(mB, mxB);
        float alA = exp2f(mA - mnA), alB = exp2f(mB - mnB);
        mA = mnA; mB = mnB;

        unsigned ph[8][2];
        float suA = 0.f, suB = 0.f;
        #pragma unroll
        for (int n = 0; n < 8; n++) {
            float p0 = exp2f(s[n][0] - mnA);
            float p1 = exp2f(s[n][1] - mnA);
            float p2 = exp2f(s[n][2] - mnB);
            float p3 = exp2f(s[n][3] - mnB);
            suA += p0 + p1; suB += p2 + p3;
            ph[n][0] = h2pack(p0, p1);   // rows rA   : A-frag (a0|a2) source
            ph[n][1] = h2pack(p2, p3);   // rows rA+8 : A-frag (a1|a3) source
        }
        suA += __shfl_xor_sync(0xffffffffu, suA, 1);
        suA += __shfl_xor_sync(0xffffffffu, suA, 2);
        suB += __shfl_xor_sync(0xffffffffu, suB, 1);
        suB += __shfl_xor_sync(0xffffffffu, suB, 2);
        lA = lA * alA + suA;
        lB = lB * alB + suB;
        #pragma unroll
        for (int n = 0; n < 8; n++) {
            o[n][0] *= alA; o[n][1] *= alA;
            o[n][2] *= alB; o[n][3] *= alB;
        }

        // ---- O += P @ V (P direct from registers; C-frag == A-frag layout) ----
        {
            int m = lane >> 3;
            #pragma unroll
            for (int kk = 0; kk < 4; kk++) {
                unsigned pa[4] = { ph[2 * kk][0], ph[2 * kk][1],
                                   ph[2 * kk + 1][0], ph[2 * kk + 1][1] };
                int vkey = kk * 16 + (m & 1) * 8 + (lane & 7);
                #pragma unroll
                for (int np = 0; np < 4; np++) {
                    unsigned vb[4];
                    ldsm4t(vb, sa(&sV[buf][vkey * HPAD + (np * 2 + (m >> 1)) * 8]));
                    mma16(o[np * 2],     pa, vb[0], vb[1]);
                    mma16(o[np * 2 + 1], pa, vb[2], vb[3]);
                }
            }
        }
        __syncthreads();   // all warps done with buf before it is refilled
    }

    float ivA = 1.f / lA, ivB = 1.f / lB;
    int gr = b * Nseq + q0 + rA;
    #pragma unroll
    for (int n = 0; n < 8; n++) {
        int c = h * Dh + n * 8 + 2 * (lane & 3);
        *(__half2*)&g_aoh[(size_t)gr * Cdim + c] =
            __floats2half2_rn(o[n][0] * ivA, o[n][1] * ivA);
        *(__half2*)&g_aoh[(size_t)(gr + 8) * Cdim + c] =
            __floats2half2_rn(o[n][2] * ivB, o[n][3] * ivB);
    }
}

// ---------------------------------------------------------------------------
// Out-proj + bias + LayerNorm, fp16 mma. BM=64, BN=256, 8 warps. (unchanged)
// ---------------------------------------------------------------------------
__global__ __launch_bounds__(256) void outlnmma_kernel(const float* __restrict__ Wo,
                                                       const float* __restrict__ bo,
                                                       const float* __restrict__ gamma,
                                                       const float* __restrict__ beta,
                                                       float* __restrict__ out)
{
    __shared__ __align__(16) __half sA[64 * HPAD];
    __shared__ __align__(16) __half sW[256 * HPAD];
    __shared__ float sStat[2][64][2];

    int tid = threadIdx.x, lane = tid & 31, warp = tid >> 5;
    int wm = warp & 3, wn = warp >> 2;
    int m = lane >> 3;
    int m0 = blockIdx.x * 64;
    float acc[16][4] = {};

    for (int k0 = 0; k0 < Cdim; k0 += 64) {
        __syncthreads();
        #pragma unroll
        for (int i = 0; i < 2; i++) {
            int fl = tid + 256 * i, r = fl >> 3, c8 = fl & 7;
            *(uint4*)&sA[r * HPAD + c8 * 8] =
                *(const uint4*)&g_aoh[(size_t)(m0 + r) * Cdim + k0 + c8 * 8];
        }
        #pragma unroll
        for (int i = 0; i < 16; i++) {
            int fl = tid + 256 * i, r = fl >> 4, c4 = (fl & 15) * 4;
            float4 w = *(const float4*)&Wo[(size_t)r * Cdim + k0 + c4];
            *(__half2*)&sW[r * HPAD + c4]     = __floats2half2_rn(w.x, w.y);
            *(__half2*)&sW[r * HPAD + c4 + 2] = __floats2half2_rn(w.z, w.w);
        }
        __syncthreads();

        #pragma unroll
        for (int ks = 0; ks < 4; ks++) {
            unsigned qa[4];
            ldsm4(qa, sa(&sA[(wm * 16 + (m & 1) * 8 + (lane & 7)) * HPAD
                             + (ks * 2 + (m >> 1)) * 8]));
            int keyb = (m >> 1) * 8 + (lane & 7);
            int ch = m & 1;
            #pragma unroll
            for (int np = 0; np < 8; np++) {
                unsigned bb[4];
                ldsm4(bb, sa(&sW[(wn * 128 + np * 16 + keyb) * HPAD
                                 + (ks * 2 + ch) * 8]));
                mma16(acc[np * 2],     qa, bb[0], bb[1]);
                mma16(acc[np * 2 + 1], qa, bb[2], bb[3]);
            }
        }
    }

    float suA = 0.f, sqA = 0.f, suB = 0.f, sqB = 0.f;
    #pragma unroll
    for (int f = 0; f < 16; f++) {
        int c = wn * 128 + (f >> 1) * 16 + (f & 1) * 8 + 2 * (lane & 3);
        float b0 = bo[c], b1 = bo[c + 1];
        acc[f][0] += b0; acc[f][1] += b1;
        acc[f][2] += b0; acc[f][3] += b1;
        suA += acc[f][0] + acc[f][1];
        sqA += acc[f][0] * acc[f][0] + acc[f][1] * acc[f][1];
        suB += acc[f][2] + acc[f][3];
        sqB += acc[f][2] * acc[f][2] + acc[f][3] * acc[f][3];
    }
    suA += __shfl_xor_sync(0xffffffffu, suA, 1);
    suA += __shfl_xor_sync(0xffffffffu, suA, 2);
    sqA += __shfl_xor_sync(0xffffffffu, sqA, 1);
    sqA += __shfl_xor_sync(0xffffffffu, sqA, 2);
    suB += __shfl_xor_sync(0xffffffffu, suB, 1);
    suB += __shfl_xor_sync(0xffffffffu, suB, 2);
    sqB += __shfl_xor_sync(0xffffffffu, sqB, 1);
    sqB += __shfl_xor_sync(0xffffffffu, sqB, 2);

    int rA = wm * 16 + (lane >> 2);
    if ((lane & 3) == 0) {
        sStat[wn][rA][0] = suA;     sStat[wn][rA][1] = sqA;
        sStat[wn][rA + 8][0] = suB; sStat[wn][rA + 8][1] = sqB;
    }
    __syncthreads();

    float sA2 = sStat[0][rA][0] + sStat[1][rA][0];
    float qA2 = sStat[0][rA][1] + sStat[1][rA][1];
    float sB2 = sStat[0][rA + 8][0] + sStat[1][rA + 8][0];
    float qB2 = sStat[0][rA + 8][1] + sStat[1][rA + 8][1];
    float muA = sA2 * (1.f / 256.f);
    float rsA = rsqrtf(qA2 * (1.f / 256.f) - muA * muA + EPSL);
    float muB = sB2 * (1.f / 256.f);
    float rsB = rsqrtf(qB2 * (1.f / 256.f) - muB * muB + EPSL);

    size_t rowA = (size_t)(m0 + rA) * Cdim;
    size_t rowB = (size_t)(m0 + rA + 8) * Cdim;
    #pragma unroll
    for (int f = 0; f < 16; f++) {
        int c = wn * 128 + (f >> 1) * 16 + (f & 1) * 8 + 2 * (lane & 3);
        float g0 = gamma[c], g1 = gamma[c + 1];
        float be0 = beta[c], be1 = beta[c + 1];
        float2 wa;
        wa.x = (acc[f][0] - muA) * rsA * g0 + be0;
        wa.y = (acc[f][1] - muA) * rsA * g1 + be1;
        *(float2*)&out[rowA + c] = wa;
        float2 wb;
        wb.x = (acc[f][2] - muB) * rsB * g0 + be0;
        wb.y = (acc[f][3] - muB) * rsB * g1 + be1;
        *(float2*)&out[rowB + c] = wb;
    }
}

// ---------------------------------------------------------------------------
extern "C" void kernel_launch(void* const* d_in, const int* in_sizes, int n_in,
                              void* d_out, int out_size)
{
    const float* x     = (const float*)d_in[0];
    const int*   adj   = (const int*)  d_in[1];
    const float* Wq    = (const float*)d_in[2];
    const float* bq    = (const float*)d_in[3];
    const float* Wk    = (const float*)d_in[4];
    const float* bk    = (const float*)d_in[5];
    const float* Wv    = (const float*)d_in[6];
    const float* bv    = (const float*)d_in[7];
    const float* Wo    = (const float*)d_in[8];
    const float* bo    = (const float*)d_in[9];
    const float* gamma = (const float*)d_in[10];
    const float* beta  = (const float*)d_in[11];
    float* out = (float*)d_out;

    x2h_kernel<<<(Bsz * Nseq * Cdim) / (256 * 4), 256>>>(x);
    pack_adj_kernel<<<(Bsz * Nseq * Nseq) / 256, 256>>>(adj);

    dim3 pgrid(Cdim / 64, (Bsz * Nseq) / 128, 3);
    projmma_kernel<<<pgrid, 128>>>(Wq, bq, Wk, bk, Wv, bv);

    dim3 fgrid(Nseq / 64, Hh, Bsz);
    flash_kernel<<<fgrid, 128>>>();

    outlnmma_kernel<<<(Bsz * Nseq) / 64, 256>>>(Wo, bo, gamma, beta, out);
}